// round 4
// baseline (speedup 1.0000x reference)
#include <cuda_runtime.h>
#include <math.h>
#include <stdint.h>

#define T_STEPS 2048
#define BATCH   64
#define HID     256
#define GATE4   1024
#define NG      (BATCH*HID)          /* 16384 */
#define REC_BLOCKS 128
#define REC_THREADS 512
#define GROUP_BLOCKS 32              /* blocks per batch-group barrier */
#define HPAD2   264                  /* padded h row stride (floats) */
#define GST     17                   /* gates_sm row stride */

typedef unsigned long long u64;

/* Scratch (device globals: no allocation allowed in kernel_launch) */
__device__ float g_xg[134217728];    /* [T][B][4H] precomputed input gates */
__device__ float g_h[2][NG];         /* double-buffered recurrent h */
__device__ unsigned g_bar4[256];     /* 4 group barriers, 256B apart */
__device__ unsigned g_done;          /* end-of-kernel reset rendezvous */

/* ---- packed f32x2 helpers (FFMA2: 2 fp32 FMA per instruction) ---- */
__device__ __forceinline__ u64 ffma2(u64 a, u64 b, u64 c){
  u64 d; asm("fma.rn.f32x2 %0, %1, %2, %3;" : "=l"(d) : "l"(a), "l"(b), "l"(c));
  return d;
}
__device__ __forceinline__ u64 fmul2(u64 a, u64 b){
  u64 d; asm("mul.rn.f32x2 %0, %1, %2;" : "=l"(d) : "l"(a), "l"(b));
  return d;
}
__device__ __forceinline__ float hadd2(u64 a){
  unsigned lo, hi;
  asm("mov.b64 {%0, %1}, %2;" : "=r"(lo), "=r"(hi) : "l"(a));
  return __uint_as_float(lo) + __uint_as_float(hi);
}
__device__ __forceinline__ void unpack2(u64 a, float& x, float& y){
  unsigned lo, hi;
  asm("mov.b64 {%0, %1}, %2;" : "=r"(lo), "=r"(hi) : "l"(a));
  x = __uint_as_float(lo); y = __uint_as_float(hi);
}
__device__ __forceinline__ u64 dup2(float x){
  u64 d; unsigned u = __float_as_uint(x);
  asm("mov.b64 %0, {%1, %1};" : "=l"(d) : "r"(u));
  return d;
}

__device__ __forceinline__ float fsigm(float x){
  return __fdividef(1.f, 1.f + __expf(-x));
}
__device__ __forceinline__ float ftanh(float x){
  return __fdividef(2.f, 1.f + __expf(-2.f*x)) - 1.f;
}
__device__ __forceinline__ unsigned ld_acq(const unsigned* p){
  unsigned v;
  asm volatile("ld.global.acquire.gpu.u32 %0, [%1];" : "=r"(v) : "l"(p) : "memory");
  return v;
}
__device__ __forceinline__ void red_rel_add(unsigned* p, unsigned v){
  asm volatile("red.release.gpu.global.add.u32 [%0], %1;" :: "l"(p), "r"(v) : "memory");
}

/* ---------------- Kernel A: x_gates = input @ W_ih^T + b_ih + b_hh ----------------
 * BM=128, BN=64, BK=16; 256 thr; TM=8 x TN=4.
 * FFMA2 over m-pairs: a-tile pairs contiguous in [k][m]; b-tile stored
 * PRE-DUPLICATED (w,w) so the inner loop is 4 LDS.128 + 16 FFMA2 per k. */
__global__ void __launch_bounds__(256, 2) xgates_gemm(
    const float* __restrict__ A, const float* __restrict__ W,
    const float* __restrict__ bih, const float* __restrict__ bhh)
{
  __shared__ float a_t[16][132];     /* [k][m], stride 132*4=528B (16B mult) */
  __shared__ u64   b_t2[16][66];     /* [k][n] duplicated pairs, 528B rows  */
  const int tid = threadIdx.x;
  const int bx = blockIdx.x, by = blockIdx.y;
  const int tx = tid & 15, ty = tid >> 4;

  u64 acc2[4][4];                    /* [m-pair][n] packed accumulators */
  #pragma unroll
  for (int mp=0;mp<4;mp++)
    #pragma unroll
    for (int n=0;n<4;n++) acc2[mp][n]=0ull;

  const float* Ab = A + (size_t)by*128*256;
  const float* Wb = W + (size_t)bx*64*256;

  for (int kt=0; kt<16; ++kt){
    const int k0 = kt*16;
    #pragma unroll
    for (int r=0;r<2;r++){
      int idx = tid + r*256;
      int row = idx >> 2, kq = idx & 3;
      float4 v = *(const float4*)(Ab + (size_t)row*256 + k0 + kq*4);
      a_t[kq*4+0][row]=v.x; a_t[kq*4+1][row]=v.y;
      a_t[kq*4+2][row]=v.z; a_t[kq*4+3][row]=v.w;
    }
    {
      int n = tid >> 2, kq = tid & 3;
      float4 v = *(const float4*)(Wb + (size_t)n*256 + k0 + kq*4);
      b_t2[kq*4+0][n]=dup2(v.x); b_t2[kq*4+1][n]=dup2(v.y);
      b_t2[kq*4+2][n]=dup2(v.z); b_t2[kq*4+3][n]=dup2(v.w);
    }
    __syncthreads();
    #pragma unroll
    for (int k=0;k<16;k++){
      ulonglong2 a01 = *(const ulonglong2*)&a_t[k][ty*8];     /* (m0,m1)(m2,m3) */
      ulonglong2 a23 = *(const ulonglong2*)&a_t[k][ty*8+4];   /* (m4,m5)(m6,m7) */
      ulonglong2 b01 = *(const ulonglong2*)&b_t2[k][tx*4];    /* (n0n0)(n1n1)   */
      ulonglong2 b23 = *(const ulonglong2*)&b_t2[k][tx*4+2];  /* (n2n2)(n3n3)   */
      acc2[0][0]=ffma2(a01.x,b01.x,acc2[0][0]); acc2[0][1]=ffma2(a01.x,b01.y,acc2[0][1]);
      acc2[0][2]=ffma2(a01.x,b23.x,acc2[0][2]); acc2[0][3]=ffma2(a01.x,b23.y,acc2[0][3]);
      acc2[1][0]=ffma2(a01.y,b01.x,acc2[1][0]); acc2[1][1]=ffma2(a01.y,b01.y,acc2[1][1]);
      acc2[1][2]=ffma2(a01.y,b23.x,acc2[1][2]); acc2[1][3]=ffma2(a01.y,b23.y,acc2[1][3]);
      acc2[2][0]=ffma2(a23.x,b01.x,acc2[2][0]); acc2[2][1]=ffma2(a23.x,b01.y,acc2[2][1]);
      acc2[2][2]=ffma2(a23.x,b23.x,acc2[2][2]); acc2[2][3]=ffma2(a23.x,b23.y,acc2[2][3]);
      acc2[3][0]=ffma2(a23.y,b01.x,acc2[3][0]); acc2[3][1]=ffma2(a23.y,b01.y,acc2[3][1]);
      acc2[3][2]=ffma2(a23.y,b23.x,acc2[3][2]); acc2[3][3]=ffma2(a23.y,b23.y,acc2[3][3]);
    }
    __syncthreads();
  }

  const int gn = bx*64 + tx*4;
  const float bb0 = bih[gn+0]+bhh[gn+0];
  const float bb1 = bih[gn+1]+bhh[gn+1];
  const float bb2 = bih[gn+2]+bhh[gn+2];
  const float bb3 = bih[gn+3]+bhh[gn+3];
  #pragma unroll
  for (int mp=0;mp<4;mp++){
    float e0,o0,e1,o1,e2,o2,e3,o3;
    unpack2(acc2[mp][0], e0, o0);
    unpack2(acc2[mp][1], e1, o1);
    unpack2(acc2[mp][2], e2, o2);
    unpack2(acc2[mp][3], e3, o3);
    int gm = by*128 + ty*8 + 2*mp;
    float4 lo = make_float4(e0+bb0, e1+bb1, e2+bb2, e3+bb3);
    float4 hi = make_float4(o0+bb0, o1+bb1, o2+bb2, o3+bb3);
    *(float4*)(g_xg + (size_t)gm*GATE4 + gn)          = lo;
    *(float4*)(g_xg + (size_t)(gm+1)*GATE4 + gn)      = hi;
  }
}

/* ---------------- Kernel B: persistent recurrence ----------------
 * 128 blocks = 4 independent batch-group chains x 32 j-groups; per-group
 * 32-block release/acquire barrier. Block: 16 batches x 8 hidden units.
 * 512 threads = (8 row-quads) x (2 batch-halves); lane: lg = k-split over 16,
 * hb = batch pair bit. W_hh rows in registers as f32x2 pairs.
 * Per pass: 4 LDS.128 + 32 FFMA2 + 4 hadd + 8 SHFL. */
__global__ void __launch_bounds__(REC_THREADS, 1) lstm_rec(
    const float* __restrict__ h0, const float* __restrict__ c0,
    const float* __restrict__ W_hh, float* __restrict__ out)
{
  __shared__ float h_sm[16*HPAD2];
  __shared__ float gates_sm[32*GST];

  const int tid  = threadIdx.x;
  const int blk  = blockIdx.x;
  const int bgid = blk & 3;
  const int jgid = blk >> 2;
  const int b0   = bgid*16;
  const int j0   = jgid*8;
  unsigned* barp = &g_bar4[bgid*64];

  const int wid  = tid >> 5, lane = tid & 31;
  const int lg   = lane & 15, hb = lane >> 4;
  const int wbh  = wid & 1;
  const int rq   = wid >> 1;

  /* W_hh rows -> registers as packed pairs. rl: gate=rl>>3, j=j0+(rl&7). */
  ulonglong2 wr2[4][4];
  #pragma unroll
  for (int r=0;r<4;r++){
    const int rl = 4*rq + r;
    const int grow = (rl>>3)*HID + j0 + (rl&7);
    #pragma unroll
    for (int q=0;q<4;q++)
      wr2[r][q] = *(const ulonglong2*)(W_hh + (size_t)grow*HID + lg*4 + 64*q);
  }

  const int jl = tid & 7, bl = (tid >> 3) & 15;
  const int eb = b0 + bl, ej = j0 + jl;
  float c_reg = 0.f, xg0=0.f, xg1=0.f, xg2=0.f, xg3=0.f;
  if (tid < 128){
    c_reg = c0[eb*HID + ej];
    const float* xp = g_xg + (size_t)eb*GATE4 + ej;   /* t = 0 */
    xg0 = xp[0]; xg1 = xp[HID]; xg2 = xp[2*HID]; xg3 = xp[3*HID];
  }

  for (int t=0; t<T_STEPS; ++t){
    /* ---- wait for previous step's h from this batch-group (acquire) */
    if (t){
      const unsigned target = (unsigned)t * GROUP_BLOCKS;
      while (ld_acq(barp) < target) { }
    }

    /* ---- stage h: 16 batches, coalesced float4, .cg (L1 would be stale) */
    const float4* hsrc = (const float4*)(((t==0) ? h0 : g_h[t & 1]) + b0*HID);
    #pragma unroll
    for (int r=0;r<2;r++){
      int fi = tid + r*512;
      int b = fi >> 6, c = fi & 63;
      float4 v = __ldcg(hsrc + b*64 + c);
      *(float4*)(h_sm + b*HPAD2 + c*4) = v;
    }
    __syncthreads();

    /* ---- compute: 4 passes of 2 batches; 4 gate-rows per warp, FFMA2 */
    #pragma unroll
    for (int p=0;p<4;p++){
      const int lb = wbh*8 + p*2 + hb;
      const float* hr = h_sm + lb*HPAD2 + lg*4;
      ulonglong2 hv0 = *(const ulonglong2*)(hr);
      ulonglong2 hv1 = *(const ulonglong2*)(hr+64);
      ulonglong2 hv2 = *(const ulonglong2*)(hr+128);
      ulonglong2 hv3 = *(const ulonglong2*)(hr+192);
      float v0, v1, v2, v3;
      #pragma unroll
      for (int r=0;r<4;r++){
        u64 s0 = fmul2(wr2[r][0].x, hv0.x);
        u64 s1 = fmul2(wr2[r][0].y, hv0.y);
        s0 = ffma2(wr2[r][1].x, hv1.x, s0);
        s1 = ffma2(wr2[r][1].y, hv1.y, s1);
        s0 = ffma2(wr2[r][2].x, hv2.x, s0);
        s1 = ffma2(wr2[r][2].y, hv2.y, s1);
        s0 = ffma2(wr2[r][3].x, hv3.x, s0);
        s1 = ffma2(wr2[r][3].y, hv3.y, s1);
        float v = hadd2(s0) + hadd2(s1);
        if (r==0) v0=v; else if (r==1) v1=v; else if (r==2) v2=v; else v3=v;
      }
      /* reduce 4 rows over 16 k-lanes: 8 SHFL (lane bit4 = hb untouched) */
      v0 += __shfl_xor_sync(0xffffffffu, v0, 8);
      v1 += __shfl_xor_sync(0xffffffffu, v1, 8);
      v2 += __shfl_xor_sync(0xffffffffu, v2, 8);
      v3 += __shfl_xor_sync(0xffffffffu, v3, 8);
      float a = (lg & 8) ? v1 : v0;
      float b = (lg & 8) ? v3 : v2;
      a += __shfl_xor_sync(0xffffffffu, a, 4);
      b += __shfl_xor_sync(0xffffffffu, b, 4);
      float x = (lg & 4) ? b : a;
      x += __shfl_xor_sync(0xffffffffu, x, 2);
      x += __shfl_xor_sync(0xffffffffu, x, 1);
      if ((lg & 3) == 0){
        const int rsel = ((lg>>3)&1) | (((lg>>2)&1)<<1);   /* 0,8,4,12 -> 0..3 */
        gates_sm[(4*rq + rsel)*GST + lb] = x;
      }
    }
    __syncthreads();

    /* ---- epilogue: activations + state update (c stays in a register) */
    float hn = 0.f;
    if (tid < 128){
      float pi = gates_sm[(0*8+jl)*GST + bl] + xg0;
      float pf = gates_sm[(1*8+jl)*GST + bl] + xg1;
      float pg = gates_sm[(2*8+jl)*GST + bl] + xg2;
      float po = gates_sm[(3*8+jl)*GST + bl] + xg3;
      float ii = fsigm(pi), ff = fsigm(pf), gg = ftanh(pg), oo = fsigm(po);
      c_reg = ff*c_reg + ii*gg;
      hn = oo * ftanh(c_reg);
      __stcg(&g_h[(t+1)&1][eb*HID + ej], hn);
    }
    __syncthreads();   /* h stores observed CTA-wide before tid0's release */

    /* ---- arrival (release), then out-stores + prefetch in its shadow */
    if (tid == 0) red_rel_add(barp, 1u);
    if (tid < 128){
      out[(size_t)t*NG + eb*HID + ej] = hn;
      if (t == T_STEPS-1){
        out[(size_t)T_STEPS*NG + eb*HID + ej]      = hn;     /* h_T */
        out[(size_t)T_STEPS*NG + NG + eb*HID + ej] = c_reg;  /* c_T */
      } else {
        const float* xp = g_xg + ((size_t)(t+1)*BATCH + eb)*GATE4 + ej;
        xg0 = xp[0]; xg1 = xp[HID]; xg2 = xp[2*HID]; xg3 = xp[3*HID];
      }
    }
  }

  /* reset counters for the next graph replay: last block to arrive does it */
  if (tid == 0){
    __threadfence();
    unsigned prev = atomicAdd(&g_done, 1u);
    if (prev == REC_BLOCKS-1){
      g_bar4[0] = 0u; g_bar4[64] = 0u; g_bar4[128] = 0u; g_bar4[192] = 0u;
      g_done = 0u;
      __threadfence();
    }
  }
}

extern "C" void kernel_launch(void* const* d_in, const int* in_sizes, int n_in,
                              void* d_out, int out_size)
{
  (void)in_sizes; (void)n_in; (void)out_size;
  const float* input = (const float*)d_in[0];
  const float* h0    = (const float*)d_in[1];
  const float* c0    = (const float*)d_in[2];
  const float* W_ih  = (const float*)d_in[3];
  const float* W_hh  = (const float*)d_in[4];
  const float* b_ih  = (const float*)d_in[5];
  const float* b_hh  = (const float*)d_in[6];
  float* out = (float*)d_out;

  xgates_gemm<<<dim3(16,1024), 256>>>(input, W_ih, b_ih, b_hh);
  lstm_rec<<<REC_BLOCKS, REC_THREADS>>>(h0, c0, W_hh, out);
}